// round 1
// baseline (speedup 1.0000x reference)
#include <cuda_runtime.h>
#include <cuda_bf16.h>

// Chamfer distance: B=16, N=M=2048, D=3.
// loss = sum_b sum_n min_m d(x_bn, y_bm) + sum_b sum_m min_n d(y_bm, x_bn)
// d expanded as |x|^2 + |y|^2 - 2 x.y (matches reference numerics).
// |x|^2 hoisted out of the min; |y_j|^2 precomputed into smem float4.w.

#define CH_B     16
#define CH_NPTS  2048
#define CH_D     3
#define CH_TPB   256

__global__ void chamfer_zero_kernel(float* out) {
    if (threadIdx.x == 0) out[0] = 0.0f;
}

__global__ __launch_bounds__(CH_TPB)
void chamfer_kernel(const float* __restrict__ preds,
                    const float* __restrict__ targs,
                    float* __restrict__ out)
{
    __shared__ float4 sRef[CH_NPTS];          // (y0, y1, y2, |y|^2)
    __shared__ float  sRed[CH_TPB / 32];

    const int dir = blockIdx.z;               // 0: preds->targs min, 1: targs->preds min
    const float* __restrict__ pts  = dir ? targs : preds;
    const float* __restrict__ refs = dir ? preds : targs;
    const int b = blockIdx.y;

    // Stage all refs for this batch into smem, with precomputed |y|^2.
    const float* refB = refs + (size_t)b * CH_NPTS * CH_D;
    for (int j = threadIdx.x; j < CH_NPTS; j += CH_TPB) {
        float r0 = refB[j * 3 + 0];
        float r1 = refB[j * 3 + 1];
        float r2 = refB[j * 3 + 2];
        sRef[j] = make_float4(r0, r1, r2, fmaf(r0, r0, fmaf(r1, r1, r2 * r2)));
    }
    __syncthreads();

    // One query point per thread.
    const int p = blockIdx.x * CH_TPB + threadIdx.x;
    const float* xp = pts + ((size_t)b * CH_NPTS + p) * CH_D;
    const float x0 = xp[0], x1 = xp[1], x2 = xp[2];
    const float xx = fmaf(x0, x0, fmaf(x1, x1, x2 * x2));

    float best = 3.402823466e38f;
    #pragma unroll 8
    for (int j = 0; j < CH_NPTS; ++j) {
        float4 r = sRef[j];                                   // LDS.128, warp-broadcast
        float s  = fmaf(x0, r.x, fmaf(x1, r.y, x2 * r.z));    // x . y_j
        float v  = fmaf(-2.0f, s, r.w);                       // |y_j|^2 - 2 x.y_j
        best = fminf(best, v);
    }
    float val = xx + best;                                    // min squared distance

    // Block sum-reduce, then one atomicAdd per block.
    #pragma unroll
    for (int o = 16; o > 0; o >>= 1)
        val += __shfl_down_sync(0xffffffffu, val, o);
    if ((threadIdx.x & 31) == 0) sRed[threadIdx.x >> 5] = val;
    __syncthreads();
    if (threadIdx.x < 32) {
        float v2 = (threadIdx.x < CH_TPB / 32) ? sRed[threadIdx.x] : 0.0f;
        #pragma unroll
        for (int o = 4; o > 0; o >>= 1)
            v2 += __shfl_down_sync(0xffffffffu, v2, o);
        if (threadIdx.x == 0) atomicAdd(out, v2);
    }
}

extern "C" void kernel_launch(void* const* d_in, const int* in_sizes, int n_in,
                              void* d_out, int out_size) {
    const float* preds = (const float*)d_in[0];
    const float* targs = (const float*)d_in[1];
    float* out = (float*)d_out;

    chamfer_zero_kernel<<<1, 32>>>(out);

    dim3 grid(CH_NPTS / CH_TPB, CH_B, 2);   // (8, 16, 2) = 256 blocks
    chamfer_kernel<<<grid, CH_TPB>>>(preds, targs, out);
}

// round 2
// speedup vs baseline: 1.3299x; 1.3299x over previous
#include <cuda_runtime.h>
#include <cuda_bf16.h>

// Chamfer distance, B=16, N=M=2048, D=3.
// v_j = |x|^2 + |y_j|^2 - 2 x.y_j ; refs pre-scaled by -2 and |y|^2 precomputed,
// so the inner body is a pure 3-deep FMA chain. Two consecutive refs are packed
// per 64-bit lane and evaluated with Blackwell packed fma.rn.f32x2 (2 pairs per
// instruction). 4 query points per thread amortize each LDS.128 over 8 pairs.

#define CH_NPTS  2048
#define CH_NPAIR (CH_NPTS / 2)     // 1024 packed ref pairs
#define CH_TPB   64
#define CH_PPT   4                 // query points per thread
#define CH_PTS_PER_BLOCK (CH_TPB * CH_PPT)   // 256
#define CH_GRIDX (CH_NPTS / CH_PTS_PER_BLOCK) // 8
#define CH_B     16

__device__ __forceinline__ unsigned long long f32x2_fma(
    unsigned long long a, unsigned long long b, unsigned long long c) {
    unsigned long long d;
    asm("fma.rn.f32x2 %0, %1, %2, %3;" : "=l"(d) : "l"(a), "l"(b), "l"(c));
    return d;
}
__device__ __forceinline__ void f32x2_unpack(unsigned long long v, float& lo, float& hi) {
    asm("mov.b64 {%0, %1}, %2;" : "=f"(lo), "=f"(hi) : "l"(v));
}
__device__ __forceinline__ unsigned long long f32x2_pack(float lo, float hi) {
    unsigned long long v;
    asm("mov.b64 %0, {%1, %2};" : "=l"(v) : "f"(lo), "f"(hi));
    return v;
}

__global__ void chamfer_zero_kernel(float* out) {
    if (threadIdx.x == 0) out[0] = 0.0f;
}

__global__ __launch_bounds__(CH_TPB)
void chamfer_kernel(const float* __restrict__ preds,
                    const float* __restrict__ targs,
                    float* __restrict__ out)
{
    // sA[jj] = { pack(-2*r0_j, -2*r0_j'), pack(-2*r1_j, -2*r1_j') }
    // sB[jj] = { pack(-2*r2_j, -2*r2_j'), pack(|r_j|^2, |r_j'|^2) }   (j'=j+1)
    __shared__ ulonglong2 sA[CH_NPAIR];
    __shared__ ulonglong2 sB[CH_NPAIR];

    const int dir = blockIdx.z;               // 0: preds->targs, 1: targs->preds
    const float* __restrict__ pts  = dir ? targs : preds;
    const float* __restrict__ refs = dir ? preds : targs;
    const int b = blockIdx.y;

    // Stage packed, pre-scaled refs.
    const float* refB = refs + (size_t)b * CH_NPTS * 3;
    for (int jj = threadIdx.x; jj < CH_NPAIR; jj += CH_TPB) {
        const float* r = refB + jj * 6;
        float a0 = r[0], a1 = r[1], a2 = r[2];
        float c0 = r[3], c1 = r[4], c2 = r[5];
        sA[jj] = make_ulonglong2(f32x2_pack(-2.0f * a0, -2.0f * c0),
                                 f32x2_pack(-2.0f * a1, -2.0f * c1));
        sB[jj] = make_ulonglong2(f32x2_pack(-2.0f * a2, -2.0f * c2),
                                 f32x2_pack(fmaf(a0, a0, fmaf(a1, a1, a2 * a2)),
                                            fmaf(c0, c0, fmaf(c1, c1, c2 * c2))));
    }
    __syncthreads();

    // Load CH_PPT query points per thread; broadcast-pack each coordinate.
    unsigned long long q0[CH_PPT], q1[CH_PPT], q2[CH_PPT];
    float xx[CH_PPT];
    const float* ptsB = pts + (size_t)b * CH_NPTS * 3;
    #pragma unroll
    for (int k = 0; k < CH_PPT; ++k) {
        int p = blockIdx.x * CH_PTS_PER_BLOCK + k * CH_TPB + threadIdx.x;
        float x0 = ptsB[p * 3 + 0];
        float x1 = ptsB[p * 3 + 1];
        float x2 = ptsB[p * 3 + 2];
        q0[k] = f32x2_pack(x0, x0);
        q1[k] = f32x2_pack(x1, x1);
        q2[k] = f32x2_pack(x2, x2);
        xx[k] = fmaf(x0, x0, fmaf(x1, x1, x2 * x2));
    }

    float mlo[CH_PPT], mhi[CH_PPT];
    #pragma unroll
    for (int k = 0; k < CH_PPT; ++k) { mlo[k] = 3.402823466e38f; mhi[k] = 3.402823466e38f; }

    #pragma unroll 4
    for (int jj = 0; jj < CH_NPAIR; ++jj) {
        ulonglong2 ra = sA[jj];     // LDS.128, warp-broadcast
        ulonglong2 rb = sB[jj];     // LDS.128, warp-broadcast
        #pragma unroll
        for (int k = 0; k < CH_PPT; ++k) {
            // v = x0*(-2r0) + x1*(-2r1) + x2*(-2r2) + |r|^2  (packed over 2 refs)
            unsigned long long t = f32x2_fma(q2[k], rb.x, rb.y);
            t = f32x2_fma(q1[k], ra.y, t);
            t = f32x2_fma(q0[k], ra.x, t);
            float lo, hi;
            f32x2_unpack(t, lo, hi);     // free: register-pair alias
            mlo[k] = fminf(mlo[k], lo);
            mhi[k] = fminf(mhi[k], hi);
        }
    }

    float val = 0.0f;
    #pragma unroll
    for (int k = 0; k < CH_PPT; ++k)
        val += xx[k] + fminf(mlo[k], mhi[k]);

    // Warp reduce + one atomic per warp.
    #pragma unroll
    for (int o = 16; o > 0; o >>= 1)
        val += __shfl_down_sync(0xffffffffu, val, o);
    if ((threadIdx.x & 31) == 0) atomicAdd(out, val);
}

extern "C" void kernel_launch(void* const* d_in, const int* in_sizes, int n_in,
                              void* d_out, int out_size) {
    const float* preds = (const float*)d_in[0];
    const float* targs = (const float*)d_in[1];
    float* out = (float*)d_out;

    chamfer_zero_kernel<<<1, 32>>>(out);

    dim3 grid(CH_GRIDX, CH_B, 2);   // (8, 16, 2) = 256 blocks
    chamfer_kernel<<<grid, CH_TPB>>>(preds, targs, out);
}

// round 3
// speedup vs baseline: 1.5918x; 1.1969x over previous
#include <cuda_runtime.h>
#include <cuda_bf16.h>

// Chamfer distance, B=16, N=M=2048, D=3 — split-refs version.
// Each block handles a 512-ref chunk for 256 query points; per-point chunk-min
// combined across blocks via atomicMin on order-preserving-encoded floats in a
// __device__ scratch array. Finalize kernel adds |x|^2 and reduces to scalar.
// Inner math: refs pre-scaled by -2, |y|^2 precomputed, packed 2 refs / 64-bit
// lane, evaluated with Blackwell fma.rn.f32x2 (3 FFMA2 + 2 FMNMX per 2 pairs).

#define CH_NPTS   2048
#define CH_B      16
#define CH_CHUNKS 4
#define CH_REFS   (CH_NPTS / CH_CHUNKS)     // 512 refs per chunk
#define CH_PAIRS  (CH_REFS / 2)             // 256 packed pairs
#define CH_TPB    128
#define CH_PPT    2                          // query points per thread
#define CH_PTSBLK (CH_TPB * CH_PPT)          // 256
#define CH_GRIDX  (CH_NPTS / CH_PTSBLK)      // 8

__device__ unsigned int g_ws[2 * CH_B * CH_NPTS];   // encoded per-point min

__device__ __forceinline__ unsigned long long f32x2_fma(
    unsigned long long a, unsigned long long b, unsigned long long c) {
    unsigned long long d;
    asm("fma.rn.f32x2 %0, %1, %2, %3;" : "=l"(d) : "l"(a), "l"(b), "l"(c));
    return d;
}
__device__ __forceinline__ void f32x2_unpack(unsigned long long v, float& lo, float& hi) {
    asm("mov.b64 {%0, %1}, %2;" : "=f"(lo), "=f"(hi) : "l"(v));
}
__device__ __forceinline__ unsigned long long f32x2_pack(float lo, float hi) {
    unsigned long long v;
    asm("mov.b64 %0, {%1, %2};" : "=l"(v) : "f"(lo), "f"(hi));
    return v;
}

// Order-preserving float<->uint map (monotone for all finite floats).
__device__ __forceinline__ unsigned enc_min(float f) {
    unsigned u = __float_as_uint(f);
    return (u & 0x80000000u) ? ~u : (u | 0x80000000u);
}
__device__ __forceinline__ float dec_min(unsigned u) {
    return (u & 0x80000000u) ? __uint_as_float(u ^ 0x80000000u)
                             : __uint_as_float(~u);
}

__global__ void chamfer_init(float* out) {
    int idx = blockIdx.x * blockDim.x + threadIdx.x;   // 64*256 = 16384 uint4
    ((uint4*)g_ws)[idx] = make_uint4(~0u, ~0u, ~0u, ~0u);
    if (idx == 0) out[0] = 0.0f;
}

__global__ __launch_bounds__(CH_TPB)
void chamfer_partial(const float* __restrict__ preds,
                     const float* __restrict__ targs)
{
    // sA[jj] = { pack(-2*r0, -2*r0'), pack(-2*r1, -2*r1') }
    // sB[jj] = { pack(-2*r2, -2*r2'), pack(|r|^2, |r'|^2) }
    __shared__ ulonglong2 sA[CH_PAIRS];
    __shared__ ulonglong2 sB[CH_PAIRS];

    const int dir = blockIdx.z >> 2;          // 0: preds->targs, 1: targs->preds
    const int c   = blockIdx.z & 3;           // ref chunk
    const float* __restrict__ pts  = dir ? targs : preds;
    const float* __restrict__ refs = dir ? preds : targs;
    const int b = blockIdx.y;

    const float* refB = refs + ((size_t)b * CH_NPTS + c * CH_REFS) * 3;
    for (int jj = threadIdx.x; jj < CH_PAIRS; jj += CH_TPB) {
        const float* r = refB + jj * 6;
        float a0 = r[0], a1 = r[1], a2 = r[2];
        float c0 = r[3], c1 = r[4], c2 = r[5];
        sA[jj] = make_ulonglong2(f32x2_pack(-2.0f * a0, -2.0f * c0),
                                 f32x2_pack(-2.0f * a1, -2.0f * c1));
        sB[jj] = make_ulonglong2(f32x2_pack(-2.0f * a2, -2.0f * c2),
                                 f32x2_pack(fmaf(a0, a0, fmaf(a1, a1, a2 * a2)),
                                            fmaf(c0, c0, fmaf(c1, c1, c2 * c2))));
    }
    __syncthreads();

    unsigned long long q0[CH_PPT], q1[CH_PPT], q2[CH_PPT];
    const float* ptsB = pts + (size_t)b * CH_NPTS * 3;
    int pbase = blockIdx.x * CH_PTSBLK + threadIdx.x;
    #pragma unroll
    for (int k = 0; k < CH_PPT; ++k) {
        int p = pbase + k * CH_TPB;
        float x0 = ptsB[p * 3 + 0];
        float x1 = ptsB[p * 3 + 1];
        float x2 = ptsB[p * 3 + 2];
        q0[k] = f32x2_pack(x0, x0);
        q1[k] = f32x2_pack(x1, x1);
        q2[k] = f32x2_pack(x2, x2);
    }

    float mlo[CH_PPT], mhi[CH_PPT];
    #pragma unroll
    for (int k = 0; k < CH_PPT; ++k) { mlo[k] = 3.402823466e38f; mhi[k] = 3.402823466e38f; }

    #pragma unroll 8
    for (int jj = 0; jj < CH_PAIRS; ++jj) {
        ulonglong2 ra = sA[jj];     // LDS.128, warp-broadcast
        ulonglong2 rb = sB[jj];     // LDS.128, warp-broadcast
        #pragma unroll
        for (int k = 0; k < CH_PPT; ++k) {
            unsigned long long t = f32x2_fma(q2[k], rb.x, rb.y);
            t = f32x2_fma(q1[k], ra.y, t);
            t = f32x2_fma(q0[k], ra.x, t);
            float lo, hi;
            f32x2_unpack(t, lo, hi);
            mlo[k] = fminf(mlo[k], lo);
            mhi[k] = fminf(mhi[k], hi);
        }
    }

    unsigned* wsB = g_ws + ((size_t)(dir * CH_B + b)) * CH_NPTS;
    #pragma unroll
    for (int k = 0; k < CH_PPT; ++k)
        atomicMin(&wsB[pbase + k * CH_TPB], enc_min(fminf(mlo[k], mhi[k])));
}

__global__ __launch_bounds__(256)
void chamfer_finalize(const float* __restrict__ preds,
                      const float* __restrict__ targs,
                      float* __restrict__ out)
{
    __shared__ float sRed[8];
    const int dir = blockIdx.z;
    const int b   = blockIdx.y;
    const int p   = blockIdx.x * 256 + threadIdx.x;
    const float* pts = dir ? targs : preds;

    const float* xp = pts + ((size_t)b * CH_NPTS + p) * 3;
    float x0 = xp[0], x1 = xp[1], x2 = xp[2];
    float xx = fmaf(x0, x0, fmaf(x1, x1, x2 * x2));
    float val = xx + dec_min(g_ws[(size_t)(dir * CH_B + b) * CH_NPTS + p]);

    #pragma unroll
    for (int o = 16; o > 0; o >>= 1)
        val += __shfl_down_sync(0xffffffffu, val, o);
    if ((threadIdx.x & 31) == 0) sRed[threadIdx.x >> 5] = val;
    __syncthreads();
    if (threadIdx.x < 32) {
        float v2 = (threadIdx.x < 8) ? sRed[threadIdx.x] : 0.0f;
        #pragma unroll
        for (int o = 4; o > 0; o >>= 1)
            v2 += __shfl_down_sync(0xffffffffu, v2, o);
        if (threadIdx.x == 0) atomicAdd(out, v2);
    }
}

extern "C" void kernel_launch(void* const* d_in, const int* in_sizes, int n_in,
                              void* d_out, int out_size) {
    const float* preds = (const float*)d_in[0];
    const float* targs = (const float*)d_in[1];
    float* out = (float*)d_out;

    chamfer_init<<<64, 256>>>(out);

    dim3 gridP(CH_GRIDX, CH_B, 2 * CH_CHUNKS);   // (8, 16, 8) = 1024 blocks
    chamfer_partial<<<gridP, CH_TPB>>>(preds, targs);

    dim3 gridF(CH_NPTS / 256, CH_B, 2);          // (8, 16, 2) = 256 blocks
    chamfer_finalize<<<gridF, 256>>>(preds, targs, out);
}